// round 1
// baseline (speedup 1.0000x reference)
#include <cuda_runtime.h>
#include <math_constants.h>

#define NPTS 8192
#define BATCH 4
#define KNN 4
#define QPB 256   // queries per block == threads per block

// Shared memory holds the whole batch point set: (x, y, z, ||x||^2) per point.
// 8192 * 16 B = 128 KB -> 1 CTA per SM.

__global__ __launch_bounds__(QPB, 1)
void knn_gather_kernel(const float* __restrict__ x, float* __restrict__ out) {
    extern __shared__ float4 pts[];  // [NPTS]

    const int b = blockIdx.y;
    const float* __restrict__ xb = x + (size_t)b * NPTS * 3;

    // ---- Stage batch points into SMEM (coalesced: consecutive threads read
    // consecutive 12B triples). Precompute ||x||^2 with the reference's
    // rounding shape: (x0*x0 + x1*x1) + x2*x2, products rounded first.
    for (int j = threadIdx.x; j < NPTS; j += QPB) {
        float px = xb[3 * j + 0];
        float py = xb[3 * j + 1];
        float pz = xb[3 * j + 2];
        float xx = __fadd_rn(__fadd_rn(__fmul_rn(px, px), __fmul_rn(py, py)),
                             __fmul_rn(pz, pz));
        pts[j] = make_float4(px, py, pz, xx);
    }
    __syncthreads();

    const int i = blockIdx.x * QPB + threadIdx.x;   // query index in [0, NPTS)
    const float4 q = pts[i];
    const float qx = q.x, qy = q.y, qz = q.z, qxx = q.w;

    // Top-4 by pd (descending), stable: earlier index wins ties (strict >).
    float v0 = -CUDART_INF_F, v1 = -CUDART_INF_F, v2 = -CUDART_INF_F, v3 = -CUDART_INF_F;
    int   i0 = 0, i1 = 0, i2 = 0, i3 = 0;

    #pragma unroll 4
    for (int j = 0; j < NPTS; ++j) {
        const float4 p = pts[j];   // broadcast LDS.128 (all lanes same addr)

        // inner = gemm-style fma chain over c = 0,1,2
        float t = __fmul_rn(qx, p.x);
        t = __fmaf_rn(qy, p.y, t);
        t = __fmaf_rn(qz, p.z, t);
        // pd = (2*inner - xx_i) - xx_j   (reference association order)
        const float pd = __fsub_rn(__fsub_rn(__fmul_rn(2.0f, t), qxx), p.w);

        if (pd > v3) {
            if (pd > v2) {
                v3 = v2; i3 = i2;
                if (pd > v1) {
                    v2 = v1; i2 = i1;
                    if (pd > v0) {
                        v1 = v0; i1 = i0;
                        v0 = pd; i0 = j;
                    } else {
                        v1 = pd; i1 = j;
                    }
                } else {
                    v2 = pd; i2 = j;
                }
            } else {
                v3 = pd; i3 = j;
            }
        }
    }

    // ---- Gather neighbor coordinates from SMEM and write out.
    // out[b][i][k][c], shape [4, 8192, 4, 3]
    float* __restrict__ o = out + (((size_t)b * NPTS + i) * KNN) * 3;
    const float4 p0 = pts[i0];
    const float4 p1 = pts[i1];
    const float4 p2 = pts[i2];
    const float4 p3 = pts[i3];
    o[0]  = p0.x; o[1]  = p0.y; o[2]  = p0.z;
    o[3]  = p1.x; o[4]  = p1.y; o[5]  = p1.z;
    o[6]  = p2.x; o[7]  = p2.y; o[8]  = p2.z;
    o[9]  = p3.x; o[10] = p3.y; o[11] = p3.z;
}

extern "C" void kernel_launch(void* const* d_in, const int* in_sizes, int n_in,
                              void* d_out, int out_size) {
    (void)n_in; (void)in_sizes; (void)out_size;
    const float* x = (const float*)d_in[0];
    float* out = (float*)d_out;

    const int smem_bytes = NPTS * (int)sizeof(float4);  // 128 KB
    static bool attr_set = false;
    // cudaFuncSetAttribute is idempotent and deterministic; safe to call every time.
    cudaFuncSetAttribute(knn_gather_kernel,
                         cudaFuncAttributeMaxDynamicSharedMemorySize, smem_bytes);
    (void)attr_set;

    dim3 grid(NPTS / QPB, BATCH, 1);   // (32, 4) = 128 blocks
    dim3 block(QPB, 1, 1);
    knn_gather_kernel<<<grid, block, smem_bytes>>>(x, out);
}

// round 2
// speedup vs baseline: 1.3717x; 1.3717x over previous
#include <cuda_runtime.h>
#include <math_constants.h>

#define NPTS 8192
#define BATCH 4
#define KNN 4
#define QPB 256   // queries per block == threads per block

// Shared memory holds the whole batch point set: (x, y, z, ||x||^2) per point.
// 8192 * 16 B = 128 KB -> 1 CTA per SM.

__global__ __launch_bounds__(QPB, 1)
void knn_gather_kernel(const float* __restrict__ x, float* __restrict__ out) {
    extern __shared__ float4 pts[];  // [NPTS]

    const int b = blockIdx.y;
    const float* __restrict__ xb = x + (size_t)b * NPTS * 3;

    // ---- Stage batch points into SMEM (coalesced: consecutive threads read
    // consecutive 12B triples). Precompute ||x||^2 with the reference's
    // rounding shape: (x0*x0 + x1*x1) + x2*x2, products rounded first.
    for (int j = threadIdx.x; j < NPTS; j += QPB) {
        float px = xb[3 * j + 0];
        float py = xb[3 * j + 1];
        float pz = xb[3 * j + 2];
        float xx = __fadd_rn(__fadd_rn(__fmul_rn(px, px), __fmul_rn(py, py)),
                             __fmul_rn(pz, pz));
        pts[j] = make_float4(px, py, pz, xx);
    }
    __syncthreads();

    const int i = blockIdx.x * QPB + threadIdx.x;   // query index in [0, NPTS)
    const float4 q = pts[i];
    const float qx = q.x, qy = q.y, qz = q.z, qxx = q.w;

    // Top-4 by pd (descending), stable: earlier index wins ties (strict >).
    float v0 = -CUDART_INF_F, v1 = -CUDART_INF_F, v2 = -CUDART_INF_F, v3 = -CUDART_INF_F;
    int   i0 = 0, i1 = 0, i2 = 0, i3 = 0;

    #pragma unroll 4
    for (int j = 0; j < NPTS; ++j) {
        const float4 p = pts[j];   // broadcast LDS.128 (all lanes same addr)

        // inner = gemm-style fma chain over c = 0,1,2
        float t = __fmul_rn(qx, p.x);
        t = __fmaf_rn(qy, p.y, t);
        t = __fmaf_rn(qz, p.z, t);
        // pd = (2*inner - xx_i) - xx_j   (reference association order)
        const float pd = __fsub_rn(__fsub_rn(__fmul_rn(2.0f, t), qxx), p.w);

        if (pd > v3) {
            if (pd > v2) {
                v3 = v2; i3 = i2;
                if (pd > v1) {
                    v2 = v1; i2 = i1;
                    if (pd > v0) {
                        v1 = v0; i1 = i0;
                        v0 = pd; i0 = j;
                    } else {
                        v1 = pd; i1 = j;
                    }
                } else {
                    v2 = pd; i2 = j;
                }
            } else {
                v3 = pd; i3 = j;
            }
        }
    }

    // ---- Gather neighbor coordinates from SMEM and write out.
    // out[b][i][k][c], shape [4, 8192, 4, 3]
    float* __restrict__ o = out + (((size_t)b * NPTS + i) * KNN) * 3;
    const float4 p0 = pts[i0];
    const float4 p1 = pts[i1];
    const float4 p2 = pts[i2];
    const float4 p3 = pts[i3];
    o[0]  = p0.x; o[1]  = p0.y; o[2]  = p0.z;
    o[3]  = p1.x; o[4]  = p1.y; o[5]  = p1.z;
    o[6]  = p2.x; o[7]  = p2.y; o[8]  = p2.z;
    o[9]  = p3.x; o[10] = p3.y; o[11] = p3.z;
}

extern "C" void kernel_launch(void* const* d_in, const int* in_sizes, int n_in,
                              void* d_out, int out_size) {
    (void)n_in; (void)in_sizes; (void)out_size;
    const float* x = (const float*)d_in[0];
    float* out = (float*)d_out;

    const int smem_bytes = NPTS * (int)sizeof(float4);  // 128 KB
    static bool attr_set = false;
    // cudaFuncSetAttribute is idempotent and deterministic; safe to call every time.
    cudaFuncSetAttribute(knn_gather_kernel,
                         cudaFuncAttributeMaxDynamicSharedMemorySize, smem_bytes);
    (void)attr_set;

    dim3 grid(NPTS / QPB, BATCH, 1);   // (32, 4) = 128 blocks
    dim3 block(QPB, 1, 1);
    knn_gather_kernel<<<grid, block, smem_bytes>>>(x, out);
}

// round 3
// speedup vs baseline: 2.0571x; 1.4996x over previous
#include <cuda_runtime.h>
#include <math_constants.h>

#define NPTS  8192
#define BATCH 4
#define KNN   4
#define QPB   224               // threads per block (7 warps)
#define GRPX  37                // ceil(NPTS / QPB) -> 37*4 = 148 blocks = 1 full wave
#define G     8                 // candidates per branch-filter group

// Shared memory: whole batch point set as (x, y, z, 0.5*||x||^2). 128 KB -> 1 CTA/SM.

__global__ __launch_bounds__(QPB, 1)
void knn_gather_kernel(const float* __restrict__ x, float* __restrict__ out) {
    extern __shared__ float4 pts[];  // [NPTS]

    const int b = blockIdx.y;
    const float* __restrict__ xb = x + (size_t)b * NPTS * 3;

    // Stage points (coalesced 12B reads), precompute h = 0.5*||p||^2.
    for (int j = threadIdx.x; j < NPTS; j += QPB) {
        float px = xb[3 * j + 0];
        float py = xb[3 * j + 1];
        float pz = xb[3 * j + 2];
        float h  = 0.5f * (px * px + py * py + pz * pz);
        pts[j] = make_float4(px, py, pz, h);
    }
    __syncthreads();

    const int i = blockIdx.x * QPB + threadIdx.x;   // query index
    if (i >= NPTS) return;

    const float4 q = pts[i];
    const float qx = q.x, qy = q.y, qz = q.z;

    // Top-4 by s = <q,p> - 0.5||p||^2 (descending). Ranking of s is identical
    // to ranking of pd = -||q-p||^2 (monotone transform; qx-terms constant).
    // Strict '>' with ascending j scan => earliest index wins ties (top_k order).
    float v0 = -CUDART_INF_F, v1 = -CUDART_INF_F, v2 = -CUDART_INF_F, v3 = -CUDART_INF_F;
    int   i0 = 0, i1 = 0, i2 = 0, i3 = 0;

    for (int j0 = 0; j0 < NPTS; j0 += G) {
        float s[G];
        #pragma unroll
        for (int e = 0; e < G; ++e) {
            const float4 p = pts[j0 + e];      // broadcast LDS.128
            float t = __fmaf_rn(qx, p.x, -p.w);
            t       = __fmaf_rn(qy, p.y, t);
            s[e]    = __fmaf_rn(qz, p.z, t);
        }
        // Branch filter: one divergent region per 8 candidates instead of per 1.
        const float m = fmaxf(fmaxf(fmaxf(s[0], s[1]), fmaxf(s[2], s[3])),
                              fmaxf(fmaxf(s[4], s[5]), fmaxf(s[6], s[7])));
        if (m > v3) {
            #pragma unroll
            for (int e = 0; e < G; ++e) {
                const float sv = s[e];
                if (sv > v3) {
                    const int j = j0 + e;
                    if (sv > v2) {
                        v3 = v2; i3 = i2;
                        if (sv > v1) {
                            v2 = v1; i2 = i1;
                            if (sv > v0) {
                                v1 = v0; i1 = i0;
                                v0 = sv; i0 = j;
                            } else { v1 = sv; i1 = j; }
                        } else { v2 = sv; i2 = j; }
                    } else { v3 = sv; i3 = j; }
                }
            }
        }
    }

    // Gather neighbor coords from SMEM; out shape [B, N, K, 3].
    float* __restrict__ o = out + (((size_t)b * NPTS + i) * KNN) * 3;
    const float4 p0 = pts[i0];
    const float4 p1 = pts[i1];
    const float4 p2 = pts[i2];
    const float4 p3 = pts[i3];
    o[0]  = p0.x; o[1]  = p0.y; o[2]  = p0.z;
    o[3]  = p1.x; o[4]  = p1.y; o[5]  = p1.z;
    o[6]  = p2.x; o[7]  = p2.y; o[8]  = p2.z;
    o[9]  = p3.x; o[10] = p3.y; o[11] = p3.z;
}

extern "C" void kernel_launch(void* const* d_in, const int* in_sizes, int n_in,
                              void* d_out, int out_size) {
    (void)n_in; (void)in_sizes; (void)out_size;
    const float* x = (const float*)d_in[0];
    float* out = (float*)d_out;

    const int smem_bytes = NPTS * (int)sizeof(float4);  // 128 KB
    cudaFuncSetAttribute(knn_gather_kernel,
                         cudaFuncAttributeMaxDynamicSharedMemorySize, smem_bytes);

    dim3 grid(GRPX, BATCH, 1);   // 37 x 4 = 148 blocks = exactly 1 wave on 148 SMs
    dim3 block(QPB, 1, 1);
    knn_gather_kernel<<<grid, block, smem_bytes>>>(x, out);
}

// round 4
// speedup vs baseline: 3.0735x; 1.4941x over previous
#include <cuda_runtime.h>
#include <math_constants.h>

#define NPTS   8192
#define BATCH  4
#define KNN    4
#define QPB    224                 // queries per block
#define SPLIT  4                   // candidate-range slices per query
#define THREADS (QPB * SPLIT)      // 896 threads = 28 warps
#define JPS    (NPTS / SPLIT)      // 2048 candidates per slice
#define G      8                   // candidates per branch-filter group
#define GRPX   37                  // ceil(8192/224) -> 148 blocks = 1 full wave

#define PTS_BYTES  (NPTS * 16)               // 131072
#define PART_N     (THREADS * KNN)           // 3584 entries
#define SMEM_BYTES (PTS_BYTES + PART_N * 8)  // +28672 -> 159744 B

__device__ __forceinline__ void insert4(float sv, int j,
                                        float& v0, float& v1, float& v2, float& v3,
                                        int& i0, int& i1, int& i2, int& i3) {
    if (sv > v3) {
        if (sv > v2) {
            v3 = v2; i3 = i2;
            if (sv > v1) {
                v2 = v1; i2 = i1;
                if (sv > v0) {
                    v1 = v0; i1 = i0;
                    v0 = sv; i0 = j;
                } else { v1 = sv; i1 = j; }
            } else { v2 = sv; i2 = j; }
        } else { v3 = sv; i3 = j; }
    }
}

__global__ __launch_bounds__(THREADS, 1)
void knn_gather_kernel(const float* __restrict__ x, float* __restrict__ out) {
    extern __shared__ char smem_raw[];
    float4* __restrict__ pts = (float4*)smem_raw;                         // [NPTS]
    float*  __restrict__ pv  = (float*)(smem_raw + PTS_BYTES);            // [PART_N]
    int*    __restrict__ pix = (int*)  (smem_raw + PTS_BYTES + PART_N*4); // [PART_N]

    const int b = blockIdx.y;
    const float* __restrict__ xb = x + (size_t)b * NPTS * 3;

    // Stage points; h = 0.5*||p||^2 so s = <q,p> - h ranks identically to -||q-p||^2.
    for (int j = threadIdx.x; j < NPTS; j += THREADS) {
        float px = xb[3 * j + 0];
        float py = xb[3 * j + 1];
        float pz = xb[3 * j + 2];
        pts[j] = make_float4(px, py, pz, 0.5f * (px * px + py * py + pz * pz));
    }
    __syncthreads();

    const int t     = threadIdx.x;
    const int qi    = t % QPB;        // query within block (warps never straddle: 224 = 7 warps)
    const int slice = t / QPB;        // candidate slice 0..3
    const int q     = blockIdx.x * QPB + qi;
    const bool active = (q < NPTS);

    float v0 = -CUDART_INF_F, v1 = -CUDART_INF_F, v2 = -CUDART_INF_F, v3 = -CUDART_INF_F;
    int   i0 = 0, i1 = 0, i2 = 0, i3 = 0;

    if (active) {
        const float4 qp = pts[q];
        const float qx = qp.x, qy = qp.y, qz = qp.z;
        const int jbase = slice * JPS;

        for (int j0 = jbase; j0 < jbase + JPS; j0 += G) {
            float s[G];
            #pragma unroll
            for (int e = 0; e < G; ++e) {
                const float4 p = pts[j0 + e];     // broadcast LDS.128
                float u = __fmaf_rn(qx, p.x, -p.w);
                u       = __fmaf_rn(qy, p.y, u);
                s[e]    = __fmaf_rn(qz, p.z, u);
            }
            const float m = fmaxf(fmaxf(fmaxf(s[0], s[1]), fmaxf(s[2], s[3])),
                                  fmaxf(fmaxf(s[4], s[5]), fmaxf(s[6], s[7])));
            if (m > v3) {
                #pragma unroll
                for (int e = 0; e < G; ++e)
                    insert4(s[e], j0 + e, v0, v1, v2, v3, i0, i1, i2, i3);
            }
        }
        // Dump sorted partial top-4 (descending, stable) to smem.
        const int base = t * KNN;
        pv[base + 0] = v0; pix[base + 0] = i0;
        pv[base + 1] = v1; pix[base + 1] = i1;
        pv[base + 2] = v2; pix[base + 2] = i2;
        pv[base + 3] = v3; pix[base + 3] = i3;
    }
    __syncthreads();

    // Slice-0 threads merge the 4 partials (slice-ascending = j-ascending => stable).
    if (active && slice == 0) {
        float w0 = -CUDART_INF_F, w1 = -CUDART_INF_F, w2 = -CUDART_INF_F, w3 = -CUDART_INF_F;
        int   k0 = 0, k1 = 0, k2 = 0, k3 = 0;
        #pragma unroll
        for (int sl = 0; sl < SPLIT; ++sl) {
            const int base = (sl * QPB + qi) * KNN;
            #pragma unroll
            for (int e = 0; e < KNN; ++e)
                insert4(pv[base + e], pix[base + e], w0, w1, w2, w3, k0, k1, k2, k3);
        }

        float* __restrict__ o = out + (((size_t)b * NPTS + q) * KNN) * 3;
        const float4 p0 = pts[k0];
        const float4 p1 = pts[k1];
        const float4 p2 = pts[k2];
        const float4 p3 = pts[k3];
        o[0]  = p0.x; o[1]  = p0.y; o[2]  = p0.z;
        o[3]  = p1.x; o[4]  = p1.y; o[5]  = p1.z;
        o[6]  = p2.x; o[7]  = p2.y; o[8]  = p2.z;
        o[9]  = p3.x; o[10] = p3.y; o[11] = p3.z;
    }
}

extern "C" void kernel_launch(void* const* d_in, const int* in_sizes, int n_in,
                              void* d_out, int out_size) {
    (void)n_in; (void)in_sizes; (void)out_size;
    const float* x = (const float*)d_in[0];
    float* out = (float*)d_out;

    cudaFuncSetAttribute(knn_gather_kernel,
                         cudaFuncAttributeMaxDynamicSharedMemorySize, SMEM_BYTES);

    dim3 grid(GRPX, BATCH, 1);   // 37 x 4 = 148 blocks
    dim3 block(THREADS, 1, 1);   // 896 threads = 28 warps/SM
    knn_gather_kernel<<<grid, block, SMEM_BYTES>>>(x, out);
}